// round 6
// baseline (speedup 1.0000x reference)
#include <cuda_runtime.h>

#define BB 16
#define DD 1024
#define HH 16
#define HDIM 64
#define TPAST 1023
#define SENC 1024
#define FFD 4096
#define ASCALE 0.125f
#define LN_EPS 1e-5f
#define VOUT 20

// ------------------------- device scratch (static, no allocation) ----------
__device__ float g_x[BB * DD];              // residual stream
__device__ float g_qkv[3 * BB * DD];        // q | k_new | v_new
__device__ float g_attn[BB * DD];           // attn output / proj input
__device__ float g_qc[BB * DD];             // cross-attn query
__device__ float g_qb[BB * HH];             // q . bk per head
__device__ float g_fold[BB * DD * HH];      // folded K direction [b][e][h]
__device__ float g_sc[BB * HH * SENC];      // cross scores -> probs in place
__device__ float g_ctx[BB * HH * DD];       // cross context [b][h][e]
__device__ float g_hbuf[BB * FFD];          // FFN hidden
__device__ float g_part[4194304];           // k-split GEMM partials (16 MB)
__device__ float g_am[BB * HH * 4];         // self-attn chunk max
__device__ float g_al[BB * HH * 4];         // self-attn chunk denom
__device__ float g_ac[BB * HH * 4 * HDIM];  // self-attn chunk numerators

struct W3 { const float* w[3]; };
struct R3 { const float* bias[3]; float* out[3]; };

// ------------------------- init: copy input x -> g_x -----------------------
__global__ void __launch_bounds__(256) init_x(const float* __restrict__ x) {
    int i = blockIdx.x * 256 + threadIdx.x;
    if (i < BB * DD) g_x[i] = x[i];
}

// ------------------------- k-split GEMM: partials --------------------------
// grid (KS, N/1024, nmats), block 256. Thread owns 4 n-cols for all 16 b rows.
__global__ void __launch_bounds__(256) gemm_part(const float* __restrict__ x, W3 mats,
                                                 float* __restrict__ part,
                                                 int N, int K, int kc) {
    __shared__ float sx[BB][16];
    const int k0 = blockIdx.x * kc;
    const float* __restrict__ W = mats.w[blockIdx.z];
    const int tid = threadIdx.x;
    for (int i = tid; i < BB * kc; i += 256) {
        int b = i / kc, kk = i - b * kc;
        sx[b][kk] = x[(size_t)b * K + k0 + kk];
    }
    __syncthreads();
    const int n = blockIdx.y * 1024 + tid * 4;
    float acc[BB][4];
#pragma unroll
    for (int b = 0; b < BB; b++) { acc[b][0] = acc[b][1] = acc[b][2] = acc[b][3] = 0.f; }
#pragma unroll 4
    for (int kk = 0; kk < kc; kk++) {
        float4 w = *(const float4*)(W + (size_t)(k0 + kk) * N + n);
#pragma unroll
        for (int b = 0; b < BB; b++) {
            float xv = sx[b][kk];
            acc[b][0] = fmaf(xv, w.x, acc[b][0]);
            acc[b][1] = fmaf(xv, w.y, acc[b][1]);
            acc[b][2] = fmaf(xv, w.z, acc[b][2]);
            acc[b][3] = fmaf(xv, w.w, acc[b][3]);
        }
    }
    float* pb = part + (size_t)(blockIdx.z * gridDim.x + blockIdx.x) * BB * N;
#pragma unroll
    for (int b = 0; b < BB; b++)
        *(float4*)(pb + (size_t)b * N + n) =
            make_float4(acc[b][0], acc[b][1], acc[b][2], acc[b][3]);
}

// ------------------------- reduce partials + bias (+relu) ------------------
// grid ((16*N)/1024, 1, nz), block 256
__global__ void __launch_bounds__(256) reduce_bias(const float* __restrict__ part, R3 p,
                                                   int N, int KS, int relu) {
    const int z = blockIdx.z;
    const float* pp = part + (size_t)z * KS * BB * N;
    int idx = (blockIdx.x * 256 + threadIdx.x) * 4;
    int b = idx / N, n = idx - b * N;
    float4 a = make_float4(0.f, 0.f, 0.f, 0.f);
#pragma unroll 4
    for (int ks = 0; ks < KS; ks++) {
        float4 v = *(const float4*)(pp + ((size_t)ks * BB + b) * N + n);
        a.x += v.x; a.y += v.y; a.z += v.z; a.w += v.w;
    }
    float4 bi = *(const float4*)(p.bias[z] + n);
    a.x += bi.x; a.y += bi.y; a.z += bi.z; a.w += bi.w;
    if (relu) {
        a.x = fmaxf(a.x, 0.f); a.y = fmaxf(a.y, 0.f);
        a.z = fmaxf(a.z, 0.f); a.w = fmaxf(a.w, 0.f);
    }
    *(float4*)(p.out[z] + (size_t)b * N + n) = a;
}

// ---------------- reduce + bias + residual + LayerNorm -> g_x --------------
__global__ void __launch_bounds__(1024) reduce_ln(const float* __restrict__ part, int KS,
                                                  const float* __restrict__ bias,
                                                  const float* __restrict__ gam,
                                                  const float* __restrict__ bet) {
    const int b = blockIdx.x, n = threadIdx.x;
    float v = 0.f;
#pragma unroll 4
    for (int ks = 0; ks < KS; ks++) v += part[((size_t)ks * BB + b) * DD + n];
    v += bias[n] + g_x[b * DD + n];
    float s = v, q = v * v;
#pragma unroll
    for (int o = 16; o; o >>= 1) {
        s += __shfl_xor_sync(0xffffffffu, s, o);
        q += __shfl_xor_sync(0xffffffffu, q, o);
    }
    __shared__ float s1[32], s2[32], mv[2];
    int w = n >> 5, ln = n & 31;
    if (ln == 0) { s1[w] = s; s2[w] = q; }
    __syncthreads();
    if (w == 0) {
        float a = s1[ln], c = s2[ln];
#pragma unroll
        for (int o = 16; o; o >>= 1) {
            a += __shfl_xor_sync(0xffffffffu, a, o);
            c += __shfl_xor_sync(0xffffffffu, c, o);
        }
        if (ln == 0) {
            float mean = a * (1.f / DD);
            mv[0] = mean;
            mv[1] = rsqrtf(c * (1.f / DD) - mean * mean + LN_EPS);
        }
    }
    __syncthreads();
    g_x[b * DD + n] = (v - mv[0]) * mv[1] * gam[n] + bet[n];
}

// ---------------- reduce cross q + per-head q.bk ---------------------------
__global__ void __launch_bounds__(1024) reduce_qc(const float* __restrict__ part, int KS,
                                                  const float* __restrict__ bias,
                                                  const float* __restrict__ bk) {
    const int b = blockIdx.x, n = threadIdx.x;
    float v = 0.f;
#pragma unroll 4
    for (int ks = 0; ks < KS; ks++) v += part[((size_t)ks * BB + b) * DD + n];
    v += bias[n];
    g_qc[b * DD + n] = v;
    float pb = v * bk[n];
#pragma unroll
    for (int o = 16; o; o >>= 1) pb += __shfl_xor_sync(0xffffffffu, pb, o);
    __shared__ float sw[32];
    if ((n & 31) == 0) sw[n >> 5] = pb;
    __syncthreads();
    if (n < HH) g_qb[b * HH + n] = sw[2 * n] + sw[2 * n + 1];
}

// ---------------- self-attention over KV cache (split-T) -------------------
// grid (16, 16, 4), block 256 (8 warps). Warp handles 32 t-values.
__global__ void __launch_bounds__(256) attn_part(const float* __restrict__ kcache,
                                                 const float* __restrict__ vcache) {
    const int b = blockIdx.x, h = blockIdx.y, c = blockIdx.z;
    const int tid = threadIdx.x, warp = tid >> 5, lane = tid & 31;
    const int bh = b * HH + h;
    const float* qp = g_qkv + b * DD + h * HDIM + lane * 2;
    const float q0 = qp[0], q1 = qp[1];
    const size_t base = (size_t)bh * TPAST * HDIM;
    const float* knew = g_qkv + BB * DD + b * DD + h * HDIM + lane * 2;
    const float* vnew = g_qkv + 2 * BB * DD + b * DD + h * HDIM + lane * 2;
    const int t0 = c * 256 + warp;
    float p[32];
#pragma unroll
    for (int j = 0; j < 32; j++) {
        int t = t0 + j * 8;
        const float* kp = (t < TPAST) ? (kcache + base + (size_t)t * HDIM + lane * 2) : knew;
        float2 kv = *(const float2*)kp;
        float s = fmaf(q0, kv.x, q1 * kv.y);
#pragma unroll
        for (int o = 16; o; o >>= 1) s += __shfl_xor_sync(0xffffffffu, s, o);
        p[j] = s * ASCALE;
    }
    float m = p[0];
#pragma unroll
    for (int j = 1; j < 32; j++) m = fmaxf(m, p[j]);
    float lsum = 0.f, a0 = 0.f, a1 = 0.f;
#pragma unroll
    for (int j = 0; j < 32; j++) {
        int t = t0 + j * 8;
        const float* vp = (t < TPAST) ? (vcache + base + (size_t)t * HDIM + lane * 2) : vnew;
        float2 vv = *(const float2*)vp;
        float e = __expf(p[j] - m);
        lsum += e;
        a0 = fmaf(e, vv.x, a0);
        a1 = fmaf(e, vv.y, a1);
    }
    __shared__ float sm[8], sl[8], sa[8][64];
    if (lane == 0) { sm[warp] = m; sl[warp] = lsum; }
    sa[warp][lane * 2] = a0;
    sa[warp][lane * 2 + 1] = a1;
    __syncthreads();
    if (tid < 64) {
        float M = sm[0];
#pragma unroll
        for (int w = 1; w < 8; w++) M = fmaxf(M, sm[w]);
        float L = 0.f, o = 0.f;
#pragma unroll
        for (int w = 0; w < 8; w++) {
            float cf = __expf(sm[w] - M);
            L = fmaf(cf, sl[w], L);
            o = fmaf(cf, sa[w][tid], o);
        }
        g_ac[(bh * 4 + c) * 64 + tid] = o;
        if (tid == 0) { g_am[bh * 4 + c] = M; g_al[bh * 4 + c] = L; }
    }
}

// ---------------- merge self-attn chunks -> g_attn -------------------------
__global__ void __launch_bounds__(64) attn_merge() {
    const int bh = blockIdx.x, d = threadIdx.x;
    float M = g_am[bh * 4];
#pragma unroll
    for (int c = 1; c < 4; c++) M = fmaxf(M, g_am[bh * 4 + c]);
    float L = 0.f, o = 0.f;
#pragma unroll
    for (int c = 0; c < 4; c++) {
        float cf = __expf(g_am[bh * 4 + c] - M);
        L = fmaf(cf, g_al[bh * 4 + c], L);
        o = fmaf(cf, g_ac[(bh * 4 + c) * 64 + d], o);
    }
    int b = bh >> 4, h = bh & 15;
    g_attn[b * DD + h * HDIM + d] = o / L;
}

// ---------------- fold K projection: g[b][e][h] ----------------------------
// grid (16 e-chunks, 16 b), block 256 (8 warps); warp handles 8 e-rows.
__global__ void __launch_bounds__(256) fold_g(const float* __restrict__ wk) {
    const int b = blockIdx.y;
    const int e0 = blockIdx.x * 64;
    const int tid = threadIdx.x, warp = tid >> 5, lane = tid & 31;
    __shared__ float sq[DD];
    for (int i = tid; i < DD; i += 256) sq[i] = g_qc[b * DD + i];
    __syncthreads();
#pragma unroll
    for (int j = 0; j < 8; j++) {
        int e = e0 + warp * 8 + j;
        const float* wr = wk + (size_t)e * DD;
        float gval = 0.f;
#pragma unroll
        for (int h = 0; h < HH; h++) {
            float s = fmaf(wr[h * 64 + lane], sq[h * 64 + lane],
                           wr[h * 64 + 32 + lane] * sq[h * 64 + 32 + lane]);
#pragma unroll
            for (int o = 16; o; o >>= 1) s += __shfl_xor_sync(0xffffffffu, s, o);
            if (lane == h) gval = s;
        }
        if (lane < HH) g_fold[((size_t)b * DD + e) * HH + lane] = gval;
    }
}

// ---------------- cross scores: enc . g + qb -------------------------------
// grid (16 s-tiles, 16 b), block 256: thread = (s_loc = tid>>2, hg = tid&3)
__global__ void __launch_bounds__(256) cross_scores(const float* __restrict__ enc) {
    const int b = blockIdx.y;
    const int s0 = blockIdx.x * 64;
    const int tid = threadIdx.x;
    const int s_loc = tid >> 2, hg = tid & 3;
    __shared__ float se[64][68];
    float acc[4] = {0.f, 0.f, 0.f, 0.f};
    for (int ec = 0; ec < 16; ec++) {
        int e0 = ec * 64;
        for (int i = tid; i < 1024; i += 256) {
            int r = i >> 4, c4 = (i & 15) * 4;
            float4 v = *(const float4*)(enc + ((size_t)(b * SENC + s0 + r)) * DD + e0 + c4);
            *(float4*)&se[r][c4] = v;
        }
        __syncthreads();
        const float* gf = g_fold + ((size_t)b * DD + e0) * HH + hg * 4;
#pragma unroll 4
        for (int e = 0; e < 64; e++) {
            float4 g4 = *(const float4*)(gf + e * HH);
            float ev = se[s_loc][e];
            acc[0] = fmaf(ev, g4.x, acc[0]);
            acc[1] = fmaf(ev, g4.y, acc[1]);
            acc[2] = fmaf(ev, g4.z, acc[2]);
            acc[3] = fmaf(ev, g4.w, acc[3]);
        }
        __syncthreads();
    }
    int s = s0 + s_loc;
#pragma unroll
    for (int i = 0; i < 4; i++) {
        int h = hg * 4 + i;
        g_sc[((size_t)(b * HH + h)) * SENC + s] = (acc[i] + g_qb[b * HH + h]) * ASCALE;
    }
}

// ---------------- softmax over s (in place) --------------------------------
__global__ void __launch_bounds__(256) softmax_sc() {
    const int bh = blockIdx.x, tid = threadIdx.x;
    float* row = g_sc + (size_t)bh * SENC;
    float4 v = *(float4*)(row + tid * 4);
    float m = fmaxf(fmaxf(v.x, v.y), fmaxf(v.z, v.w));
#pragma unroll
    for (int o = 16; o; o >>= 1) m = fmaxf(m, __shfl_xor_sync(0xffffffffu, m, o));
    __shared__ float sh[8], sh2[8];
    int w = tid >> 5, ln = tid & 31;
    if (ln == 0) sh[w] = m;
    __syncthreads();
    float M = sh[0];
#pragma unroll
    for (int i = 1; i < 8; i++) M = fmaxf(M, sh[i]);
    float e0 = __expf(v.x - M), e1 = __expf(v.y - M);
    float e2 = __expf(v.z - M), e3 = __expf(v.w - M);
    float s = e0 + e1 + e2 + e3;
#pragma unroll
    for (int o = 16; o; o >>= 1) s += __shfl_xor_sync(0xffffffffu, s, o);
    if (ln == 0) sh2[w] = s;
    __syncthreads();
    float S = sh2[0];
#pragma unroll
    for (int i = 1; i < 8; i++) S += sh2[i];
    float r = 1.f / S;
    *(float4*)(row + tid * 4) = make_float4(e0 * r, e1 * r, e2 * r, e3 * r);
}

// ---------------- cross context: ctx[b][h][e] = sum_s p * enc --------------
// grid (16 e-tiles, 16 b), block 256: thread = (e_loc = tid&63, hg = tid>>6)
__global__ void __launch_bounds__(256) cross_ctx(const float* __restrict__ enc) {
    const int b = blockIdx.y;
    const int e0 = blockIdx.x * 64;
    const int tid = threadIdx.x;
    const int e_loc = tid & 63, hg = tid >> 6;
    __shared__ float sp[16][65];
    float acc[4] = {0.f, 0.f, 0.f, 0.f};
    for (int sc = 0; sc < 16; sc++) {
        int s0 = sc * 64;
        for (int i = tid; i < 1024; i += 256) {
            int h = i >> 6, sl = i & 63;
            sp[h][sl] = g_sc[((size_t)(b * HH + h)) * SENC + s0 + sl];
        }
        __syncthreads();
        const float* ep = enc + ((size_t)(b * SENC + s0)) * DD + e0 + e_loc;
#pragma unroll 4
        for (int sl = 0; sl < 64; sl++) {
            float ev = ep[(size_t)sl * DD];
#pragma unroll
            for (int i = 0; i < 4; i++) acc[i] = fmaf(ev, sp[hg * 4 + i][sl], acc[i]);
        }
        __syncthreads();
    }
#pragma unroll
    for (int i = 0; i < 4; i++)
        g_ctx[((size_t)(b * HH + hg * 4 + i)) * DD + e0 + e_loc] = acc[i];
}

// ---------------- folded V projection partials -----------------------------
// grid (128, 1, 1), block 256; out[b,n] = sum_e ctx[b,h(n),e] * wv[e,n]
__global__ void __launch_bounds__(256) vproj_part(const float* __restrict__ W,
                                                  float* __restrict__ part) {
    const int k0 = blockIdx.x * 8;
    const int tid = threadIdx.x;
    __shared__ float sx[256][8];
    {
        float4 a = *(const float4*)(g_ctx + (size_t)tid * DD + k0);
        float4 c = *(const float4*)(g_ctx + (size_t)tid * DD + k0 + 4);
        sx[tid][0] = a.x; sx[tid][1] = a.y; sx[tid][2] = a.z; sx[tid][3] = a.w;
        sx[tid][4] = c.x; sx[tid][5] = c.y; sx[tid][6] = c.z; sx[tid][7] = c.w;
    }
    __syncthreads();
    const int n = tid * 4;
    const int h = n >> 6;
    float acc[BB][4];
#pragma unroll
    for (int b = 0; b < BB; b++) { acc[b][0] = acc[b][1] = acc[b][2] = acc[b][3] = 0.f; }
#pragma unroll
    for (int kk = 0; kk < 8; kk++) {
        float4 w = *(const float4*)(W + (size_t)(k0 + kk) * DD + n);
#pragma unroll
        for (int b = 0; b < BB; b++) {
            float xv = sx[b * HH + h][kk];
            acc[b][0] = fmaf(xv, w.x, acc[b][0]);
            acc[b][1] = fmaf(xv, w.y, acc[b][1]);
            acc[b][2] = fmaf(xv, w.z, acc[b][2]);
            acc[b][3] = fmaf(xv, w.w, acc[b][3]);
        }
    }
    float* pb = part + (size_t)blockIdx.x * BB * DD;
#pragma unroll
    for (int b = 0; b < BB; b++)
        *(float4*)(pb + (size_t)b * DD + n) =
            make_float4(acc[b][0], acc[b][1], acc[b][2], acc[b][3]);
}

// ---------------- final logits ---------------------------------------------
__global__ void __launch_bounds__(256) final_logits(const float* __restrict__ wout,
                                                    const float* __restrict__ bout,
                                                    float* __restrict__ out) {
    const int b = blockIdx.x, v = blockIdx.y, tid = threadIdx.x;
    float s = 0.f;
    for (int d = tid; d < DD; d += 256) s = fmaf(g_x[b * DD + d], wout[d * VOUT + v], s);
#pragma unroll
    for (int o = 16; o; o >>= 1) s += __shfl_xor_sync(0xffffffffu, s, o);
    __shared__ float sw[8];
    if ((tid & 31) == 0) sw[tid >> 5] = s;
    __syncthreads();
    if (tid == 0) {
        float t = sw[0];
#pragma unroll
        for (int i = 1; i < 8; i++) t += sw[i];
        out[b * VOUT + v] = t + bout[v];
    }
}

// ===========================================================================
extern "C" void kernel_launch(void* const* d_in, const int* in_sizes, int n_in,
                              void* d_out, int out_size) {
    const float* x      = (const float*)d_in[0];
    const float* enc    = (const float*)d_in[1];
    const float* kcache = (const float*)d_in[2];
    const float* vcache = (const float*)d_in[3];
    const float* wq_s = (const float*)d_in[4];
    const float* bq_s = (const float*)d_in[5];
    const float* wk_s = (const float*)d_in[6];
    const float* bk_s = (const float*)d_in[7];
    const float* wv_s = (const float*)d_in[8];
    const float* bv_s = (const float*)d_in[9];
    const float* wo_s = (const float*)d_in[10];
    const float* bo_s = (const float*)d_in[11];
    const float* wq_c = (const float*)d_in[12];
    const float* bq_c = (const float*)d_in[13];
    const float* wk_c = (const float*)d_in[14];
    const float* bk_c = (const float*)d_in[15];
    const float* wv_c = (const float*)d_in[16];
    const float* bv_c = (const float*)d_in[17];
    const float* wo_c = (const float*)d_in[18];
    const float* bo_c = (const float*)d_in[19];
    const float* w1   = (const float*)d_in[20];
    const float* b1   = (const float*)d_in[21];
    const float* w2   = (const float*)d_in[22];
    const float* b2   = (const float*)d_in[23];
    const float* ln1_g = (const float*)d_in[24];
    const float* ln1_b = (const float*)d_in[25];
    const float* ln2_g = (const float*)d_in[26];
    const float* ln2_b = (const float*)d_in[27];
    const float* ln3_g = (const float*)d_in[28];
    const float* ln3_b = (const float*)d_in[29];
    const float* w_out = (const float*)d_in[30];
    const float* b_out = (const float*)d_in[31];

    void* pv;
    cudaGetSymbolAddress(&pv, g_x);    float* p_gx   = (float*)pv;
    cudaGetSymbolAddress(&pv, g_qkv);  float* p_qkv  = (float*)pv;
    cudaGetSymbolAddress(&pv, g_attn); float* p_attn = (float*)pv;
    cudaGetSymbolAddress(&pv, g_hbuf); float* p_hbuf = (float*)pv;
    cudaGetSymbolAddress(&pv, g_part); float* p_part = (float*)pv;

    const size_t DSQ = (size_t)DD * DD;
    const size_t CACHE_L = (size_t)BB * HH * TPAST * HDIM;

    init_x<<<64, 256>>>(x);

    for (int l = 0; l < 3; l++) {
        const size_t mm = (size_t)l * DSQ;
        const size_t vv = (size_t)l * DD;

        // ---- self-attention ----
        W3 wqkv = {{wq_s + mm, wk_s + mm, wv_s + mm}};
        gemm_part<<<dim3(64, 1, 3), 256>>>(p_gx, wqkv, p_part, DD, DD, 16);
        R3 r1 = {{bq_s + vv, bk_s + vv, bv_s + vv},
                 {p_qkv, p_qkv + BB * DD, p_qkv + 2 * BB * DD}};
        reduce_bias<<<dim3(16, 1, 3), 256>>>(p_part, r1, DD, 64, 0);
        attn_part<<<dim3(16, 16, 4), 256>>>(kcache + l * CACHE_L, vcache + l * CACHE_L);
        attn_merge<<<256, 64>>>();
        W3 wos = {{wo_s + mm, 0, 0}};
        gemm_part<<<dim3(128, 1, 1), 256>>>(p_attn, wos, p_part, DD, DD, 8);
        reduce_ln<<<16, 1024>>>(p_part, 128, bo_s + vv, ln1_g + vv, ln1_b + vv);

        // ---- cross-attention (folded) ----
        W3 wqc = {{wq_c + mm, 0, 0}};
        gemm_part<<<dim3(128, 1, 1), 256>>>(p_gx, wqc, p_part, DD, DD, 8);
        reduce_qc<<<16, 1024>>>(p_part, 128, bq_c + vv, bk_c + vv);
        fold_g<<<dim3(16, 16), 256>>>(wk_c + mm);
        cross_scores<<<dim3(16, 16), 256>>>(enc);
        softmax_sc<<<256, 256>>>();
        cross_ctx<<<dim3(16, 16), 256>>>(enc);
        vproj_part<<<128, 256>>>(wv_c + mm, p_part);
        R3 r2 = {{bv_c + vv, 0, 0}, {p_attn, 0, 0}};
        reduce_bias<<<dim3(16, 1, 1), 256>>>(p_part, r2, DD, 128, 0);
        W3 woc = {{wo_c + mm, 0, 0}};
        gemm_part<<<dim3(128, 1, 1), 256>>>(p_attn, woc, p_part, DD, DD, 8);
        reduce_ln<<<16, 1024>>>(p_part, 128, bo_c + vv, ln2_g + vv, ln2_b + vv);

        // ---- FFN ----
        W3 ww1 = {{w1 + (size_t)l * DD * FFD, 0, 0}};
        gemm_part<<<dim3(64, 4, 1), 256>>>(p_gx, ww1, p_part, FFD, DD, 16);
        R3 r3 = {{b1 + (size_t)l * FFD, 0, 0}, {p_hbuf, 0, 0}};
        reduce_bias<<<dim3(64, 1, 1), 256>>>(p_part, r3, FFD, 64, 1);
        W3 ww2 = {{w2 + (size_t)l * FFD * DD, 0, 0}};
        gemm_part<<<dim3(256, 1, 1), 256>>>(p_hbuf, ww2, p_part, DD, FFD, 16);
        reduce_ln<<<16, 1024>>>(p_part, 256, b2 + vv, ln3_g + vv, ln3_b + vv);
    }

    final_logits<<<dim3(16, VOUT), 256>>>(w_out, b_out, (float*)d_out);
}